// round 1
// baseline (speedup 1.0000x reference)
#include <cuda_runtime.h>
#include <cuda_bf16.h>
#include <math.h>

// Problem constants (fixed by the dataset)
#define D_MODEL 256
#define NHEAD   8
#define HEADDIM 32
#define NQ      100
#define MAX_TOK 65536
#define MAX_BNQ 1600   // B*NQ

// ---------------- scratch (static device arrays; no allocation) -------------
__device__ float g_K[(size_t)MAX_TOK * D_MODEL];     // 64 MiB
__device__ float g_V[(size_t)MAX_TOK * D_MODEL];     // 64 MiB
__device__ float g_Qs[(size_t)MAX_BNQ * D_MODEL];    // scaled q projection
__device__ float g_ctx[(size_t)MAX_BNQ * D_MODEL];   // attention context

// ---------------- GEMM: C = (A @ W^T + bias) * scale (+ res) ----------------
// A: M x K row-major, W: N x K row-major (torch Linear weight), K==N==256 here.
// Block tile 128x64, BK=16, 256 threads, 8x4 microtile per thread.
#define BM 128
#define BN 64
#define BK 16

__global__ __launch_bounds__(256)
void gemm_bias_kernel(const float* __restrict__ A, const float* __restrict__ W,
                      const float* __restrict__ bias, const float* __restrict__ res,
                      float* __restrict__ C, int M, int N, int K,
                      float scale, int add_res)
{
    __shared__ float As[BK][BM];
    __shared__ float Ws[BK][BN];

    const int m0 = blockIdx.y * BM;
    const int n0 = blockIdx.x * BN;
    const int t  = threadIdx.x;          // 0..255
    const int tx = t & 15;               // 0..15 -> 4 cols each
    const int ty = t >> 4;               // 0..15 -> 8 rows each

    float acc[8][4];
#pragma unroll
    for (int i = 0; i < 8; i++)
#pragma unroll
        for (int j = 0; j < 4; j++) acc[i][j] = 0.f;

    for (int k0 = 0; k0 < K; k0 += BK) {
        // load A tile: 128x16 = 512 float4, 2 per thread
#pragma unroll
        for (int r = 0; r < 2; r++) {
            int idx = t + r * 256;       // 0..511
            int row = idx >> 2;          // 0..127
            int cg  = (idx & 3) * 4;     // 0,4,8,12
            int gm  = m0 + row;
            float4 v = make_float4(0.f, 0.f, 0.f, 0.f);
            if (gm < M)
                v = *reinterpret_cast<const float4*>(A + (size_t)gm * K + k0 + cg);
            As[cg + 0][row] = v.x; As[cg + 1][row] = v.y;
            As[cg + 2][row] = v.z; As[cg + 3][row] = v.w;
        }
        // load W tile: 64x16 = 256 float4, 1 per thread
        {
            int row = t >> 2;            // 0..63
            int cg  = (t & 3) * 4;
            int gn  = n0 + row;
            float4 v = make_float4(0.f, 0.f, 0.f, 0.f);
            if (gn < N)
                v = *reinterpret_cast<const float4*>(W + (size_t)gn * K + k0 + cg);
            Ws[cg + 0][row] = v.x; Ws[cg + 1][row] = v.y;
            Ws[cg + 2][row] = v.z; Ws[cg + 3][row] = v.w;
        }
        __syncthreads();

#pragma unroll
        for (int kk = 0; kk < BK; kk++) {
            float a[8], w[4];
#pragma unroll
            for (int i = 0; i < 8; i++) a[i] = As[kk][ty * 8 + i];
#pragma unroll
            for (int j = 0; j < 4; j++) w[j] = Ws[kk][tx * 4 + j];
#pragma unroll
            for (int i = 0; i < 8; i++)
#pragma unroll
                for (int j = 0; j < 4; j++)
                    acc[i][j] = fmaf(a[i], w[j], acc[i][j]);
        }
        __syncthreads();
    }

#pragma unroll
    for (int i = 0; i < 8; i++) {
        int gm = m0 + ty * 8 + i;
        if (gm >= M) continue;
#pragma unroll
        for (int j = 0; j < 4; j++) {
            int gn = n0 + tx * 4 + j;
            float v = (acc[i][j] + bias[gn]) * scale;
            if (add_res) v += res[(size_t)gm * N + gn];
            C[(size_t)gm * N + gn] = v;
        }
    }
}

// ---------------- attention: per (qchunk, head, batch) block ----------------
// 128 threads = 4 warps; each warp owns 8 queries; lane == head-dim index.
#define KT 64

__global__ __launch_bounds__(128)
void attn_kernel(const float* __restrict__ Qs, const float* __restrict__ Kg,
                 const float* __restrict__ Vg, const int* __restrict__ offs,
                 float* __restrict__ ctx)
{
    const int chunk = blockIdx.x;  // 0..3 (32 queries each)
    const int h     = blockIdx.y;  // head
    const int b     = blockIdx.z;  // batch
    const int t     = threadIdx.x;
    const int w     = t >> 5;
    const int lane  = t & 31;

    __shared__ float qs[32][32];       // [query][dim]
    __shared__ float Ks[KT][33];       // padded rows
    __shared__ float Vs[KT][33];

    const int off0 = offs[b];
    const int len  = offs[b + 1] - off0;

    // load q chunk (32 queries x 32 dims), zero-pad invalid queries
#pragma unroll
    for (int r = 0; r < 2; r++) {
        int idx = t * 2 + r;             // 0..255 float4 index
        int row = idx >> 3;              // 0..31
        int cg  = (idx & 7) * 4;         // 0..28
        int nq  = chunk * 32 + row;
        float4 v = make_float4(0.f, 0.f, 0.f, 0.f);
        if (nq < NQ)
            v = *reinterpret_cast<const float4*>(
                    Qs + ((size_t)(b * NQ + nq)) * D_MODEL + h * HEADDIM + cg);
        qs[row][cg + 0] = v.x; qs[row][cg + 1] = v.y;
        qs[row][cg + 2] = v.z; qs[row][cg + 3] = v.w;
    }

    float o[8], m[8], l[8];
#pragma unroll
    for (int q = 0; q < 8; q++) { o[q] = 0.f; m[q] = -INFINITY; l[q] = 0.f; }

    const int qrow = w * 8;

    for (int kt = 0; kt < len; kt += KT) {
        __syncthreads();
        // load K,V tiles: 64x32 each = 512 float4 each, 4 per thread each
#pragma unroll
        for (int r = 0; r < 4; r++) {
            int idx = t + r * 128;       // 0..511
            int row = idx >> 3;          // 0..63
            int cg  = (idx & 7) * 4;
            int key = kt + row;
            float4 kv = make_float4(0.f, 0.f, 0.f, 0.f);
            float4 vv = make_float4(0.f, 0.f, 0.f, 0.f);
            if (key < len) {
                size_t base = ((size_t)(off0 + key)) * D_MODEL + h * HEADDIM + cg;
                kv = *reinterpret_cast<const float4*>(Kg + base);
                vv = *reinterpret_cast<const float4*>(Vg + base);
            }
            Ks[row][cg + 0] = kv.x; Ks[row][cg + 1] = kv.y;
            Ks[row][cg + 2] = kv.z; Ks[row][cg + 3] = kv.w;
            Vs[row][cg + 0] = vv.x; Vs[row][cg + 1] = vv.y;
            Vs[row][cg + 2] = vv.z; Vs[row][cg + 3] = vv.w;
        }
        __syncthreads();

        const bool valid0 = (kt + lane) < len;
        const bool valid1 = (kt + 32 + lane) < len;

        float s0[8], s1[8];
#pragma unroll
        for (int q = 0; q < 8; q++) { s0[q] = 0.f; s1[q] = 0.f; }

#pragma unroll
        for (int d = 0; d < 32; d++) {
            float k0 = Ks[lane][d];
            float k1 = Ks[lane + 32][d];
#pragma unroll
            for (int q = 0; q < 8; q++) {
                float qd = qs[qrow + q][d];
                s0[q] = fmaf(qd, k0, s0[q]);
                s1[q] = fmaf(qd, k1, s1[q]);
            }
        }

#pragma unroll
        for (int q = 0; q < 8; q++) {
            float a  = valid0 ? s0[q] : -INFINITY;
            float bb = valid1 ? s1[q] : -INFINITY;
            float mx = fmaxf(a, bb);
#pragma unroll
            for (int off = 16; off; off >>= 1)
                mx = fmaxf(mx, __shfl_xor_sync(0xffffffffu, mx, off));
            float m_new = fmaxf(m[q], mx);
            float p0 = __expf(a - m_new);
            float p1 = __expf(bb - m_new);
            float ps = p0 + p1;
#pragma unroll
            for (int off = 16; off; off >>= 1)
                ps += __shfl_xor_sync(0xffffffffu, ps, off);
            float alpha = __expf(m[q] - m_new);
            l[q] = l[q] * alpha + ps;
            float oq = o[q] * alpha;
#pragma unroll
            for (int kk = 0; kk < 32; kk++)
                oq = fmaf(__shfl_sync(0xffffffffu, p0, kk), Vs[kk][lane], oq);
#pragma unroll
            for (int kk = 0; kk < 32; kk++)
                oq = fmaf(__shfl_sync(0xffffffffu, p1, kk), Vs[kk + 32][lane], oq);
            o[q] = oq;
            m[q] = m_new;
        }
    }

#pragma unroll
    for (int q = 0; q < 8; q++) {
        int nq = chunk * 32 + qrow + q;
        if (nq < NQ) {
            float val = (l[q] > 0.f) ? (o[q] / l[q]) : 0.f;
            ctx[((size_t)(b * NQ + nq)) * D_MODEL + h * HEADDIM + lane] = val;
        }
    }
}

// ---------------- launch --------------------------------------------------
extern "C" void kernel_launch(void* const* d_in, const int* in_sizes, int n_in,
                              void* d_out, int out_size)
{
    const float* source = (const float*)d_in[0];
    const float* query  = (const float*)d_in[1];
    const int*   offs   = (const int*)  d_in[2];
    const float* Wq = (const float*)d_in[3];  const float* bq = (const float*)d_in[4];
    const float* Wk = (const float*)d_in[5];  const float* bk = (const float*)d_in[6];
    const float* Wv = (const float*)d_in[7];  const float* bv = (const float*)d_in[8];
    const float* Wo = (const float*)d_in[9];  const float* bo = (const float*)d_in[10];
    float* out = (float*)d_out;

    const int Ntok = in_sizes[0] / D_MODEL;              // 65536
    const int B    = in_sizes[1] / (NQ * D_MODEL);       // 16
    const int Mq   = B * NQ;                             // 1600
    const float scale = 1.0f / sqrtf((float)HEADDIM);

    float *pK, *pV, *pQs, *pCtx;
    cudaGetSymbolAddress((void**)&pK,  g_K);
    cudaGetSymbolAddress((void**)&pV,  g_V);
    cudaGetSymbolAddress((void**)&pQs, g_Qs);
    cudaGetSymbolAddress((void**)&pCtx, g_ctx);

    dim3 blk(256);

    // q projection (scaled)
    {
        dim3 grid(D_MODEL / BN, (Mq + BM - 1) / BM);
        gemm_bias_kernel<<<grid, blk>>>(query, Wq, bq, nullptr, pQs,
                                        Mq, D_MODEL, D_MODEL, scale, 0);
    }
    // K projection
    {
        dim3 grid(D_MODEL / BN, (Ntok + BM - 1) / BM);
        gemm_bias_kernel<<<grid, blk>>>(source, Wk, bk, nullptr, pK,
                                        Ntok, D_MODEL, D_MODEL, 1.0f, 0);
    }
    // V projection
    {
        dim3 grid(D_MODEL / BN, (Ntok + BM - 1) / BM);
        gemm_bias_kernel<<<grid, blk>>>(source, Wv, bv, nullptr, pV,
                                        Ntok, D_MODEL, D_MODEL, 1.0f, 0);
    }
    // attention
    {
        dim3 grid((NQ + 31) / 32, NHEAD, B);
        attn_kernel<<<grid, 128>>>(pQs, pK, pV, offs, pCtx);
    }
    // out projection + bias + residual
    {
        dim3 grid(D_MODEL / BN, (Mq + BM - 1) / BM);
        gemm_bias_kernel<<<grid, blk>>>(pCtx, Wo, bo, query, out,
                                        Mq, D_MODEL, D_MODEL, 1.0f, 1);
    }
}